// round 15
// baseline (speedup 1.0000x reference)
#include <cuda_runtime.h>
#include <math.h>

// Problem constants
#define Bn 256
#define Tn 512
#define En 128
#define Hn 256

typedef unsigned long long ull;

// ---------------- device scratch (static; no runtime allocation) ----------------
__device__ __align__(16) float g_xp[2 * Tn * Bn * 768];   // [dir][t][sb][768] fp32
__device__ __align__(16) ull   g_h2[2 * 2 * 128 * Bn];    // [par][dir][k2][bglob] (k-paired h)
__device__ __align__(16) float g_hfinal[2 * Bn * Hn];     // [dir][sb][j]
__device__ int   g_perm[Bn];                  // sorted pos -> original batch idx
__device__ int   g_slen[Bn];                  // lens sorted descending
__device__ unsigned g_barG[8 * 32];           // 8 group barrier counters, 128B apart

// ---------------- helpers ----------------
__device__ __forceinline__ void fma2(ull &a, ull x, ull y) {
    asm("fma.rn.f32x2 %0, %1, %2, %0;" : "+l"(a) : "l"(x), "l"(y));
}
__device__ __forceinline__ float f2lo(ull v) { return __uint_as_float((unsigned)(v & 0xffffffffull)); }
__device__ __forceinline__ float f2hi(ull v) { return __uint_as_float((unsigned)(v >> 32)); }
__device__ __forceinline__ ull pk(unsigned lo, unsigned hi) { return ((ull)hi << 32) | (ull)lo; }
__device__ __forceinline__ float sigmf(float x) {
    float e = __expf(-fabsf(x));
    float s = __fdividef(1.f, 1.f + e);
    return (x >= 0.f) ? s : 1.f - s;
}
__device__ __forceinline__ float tanhf_fast(float x) {
    float e = __expf(-2.f * fabsf(x));
    float th = __fdividef(1.f - e, 1.f + e);
    return (x >= 0.f) ? th : -th;
}

// ---------------- prep: sort batches by len desc, zero h2 parity0, reset barriers -
__global__ void prep_kernel(const int* __restrict__ lens) {
    __shared__ int sl[Bn];
    int i = threadIdx.x;
    sl[i] = lens[i];
    __syncthreads();
    int li = sl[i];
    int rank = 0;
    #pragma unroll 8
    for (int j = 0; j < Bn; j++) {
        int lj = sl[j];
        rank += (lj > li) || (lj == li && j < i);
    }
    g_perm[rank] = i;
    g_slen[rank] = li;
    g_barG[i] = 0u;                            // i < 256 covers all 8*32 slots
    // zero parity-0 h2 buffer: first 2*128*Bn ulls ([par=0][dir][k2][b])
    for (int f = i; f < 2 * 128 * Bn; f += Bn) g_h2[f] = 0ull;
}

// ---------------- dummy: aligns rec_kernel onto the profiler's capture slot ------
__global__ void dummy_kernel() {}

// ---------------- phase 1: xp[d][t][sb][g] = x @ W_ih^T + b_ih (R11 proven) -------
#define XPAD 65
#define XP_SMEM (2 * 128 * XPAD * 4)          // 66560 B
__global__ __launch_bounds__(256) void xp_kernel(
    const int* __restrict__ seqs, const int* __restrict__ lens,
    const float* __restrict__ embed,
    const float* __restrict__ Wf, const float* __restrict__ Wb,
    const float* __restrict__ bf, const float* __restrict__ bb)
{
    extern __shared__ float sm[];
    float* x_s = sm;                 // [k=128][t=64] stride XPAD
    float* w_s = sm + 128 * XPAD;    // [k=128][g=64] stride XPAD

    int d = blockIdx.x >> 3;
    int chunk = blockIdx.x & 7;
    int sb = blockIdx.y;
    int b = g_perm[sb];
    int len = lens[b];
    int t0 = chunk * 64;
    if (t0 >= len) return;

    const float* W = d ? Wb : Wf;
    const float* bi = d ? bb : bf;
    int tid = threadIdx.x;

    for (int f = tid; f < 64 * 128; f += 256) {
        int tt = f >> 7, k = f & 127;
        int t = t0 + tt;
        int pos = d ? max(len - 1 - t, 0) : t;
        int tok = seqs[b * Tn + pos];
        x_s[k * XPAD + tt] = embed[tok * En + k];
    }

    int tx = tid & 15;
    int ty = tid >> 4;

    for (int gt = 0; gt < 12; gt++) {     // 12 * 64 = 768 = 3H
        __syncthreads();
        for (int f = tid; f < 64 * 128; f += 256) {
            int g = f >> 7, k = f & 127;
            w_s[k * XPAD + g] = W[(gt * 64 + g) * En + k];
        }
        __syncthreads();

        float acc[4][4];
        #pragma unroll
        for (int i = 0; i < 4; i++)
            #pragma unroll
            for (int jj = 0; jj < 4; jj++) acc[i][jj] = 0.f;

        #pragma unroll 4
        for (int k = 0; k < 128; k++) {
            float xv[4], wv[4];
            #pragma unroll
            for (int i = 0; i < 4; i++) xv[i] = x_s[k * XPAD + tx * 4 + i];
            #pragma unroll
            for (int jj = 0; jj < 4; jj++) wv[jj] = w_s[k * XPAD + ty * 4 + jj];
            #pragma unroll
            for (int i = 0; i < 4; i++)
                #pragma unroll
                for (int jj = 0; jj < 4; jj++)
                    acc[i][jj] = fmaf(xv[i], wv[jj], acc[i][jj]);
        }

        float4 b4 = *(const float4*)&bi[gt * 64 + ty * 4];
        #pragma unroll
        for (int i = 0; i < 4; i++) {
            int t = t0 + tx * 4 + i;
            float4 o;
            o.x = acc[i][0] + b4.x; o.y = acc[i][1] + b4.y;
            o.z = acc[i][2] + b4.z; o.w = acc[i][3] + b4.w;
            *(float4*)&g_xp[((d * Tn + t) * Bn + sb) * 768 + gt * 64 + ty * 4] = o;
        }
    }
}

// ---------------- phase 2: persistent recurrence, 128 CTAs x 512 threads ----------
// CTA = (dir, sb-tile 64, j-tile 16). Lane map: jl = (w&1)*8 + (lane&7),
// bq = (w>>1)*4 + (lane>>3) in 0..31; each thread owns 2 batches, 3 gate rows.
// f32x2 packs k-parity (even,odd) partials; 4 warps/SMSP for latency hiding.
// GROUP-LOCAL barrier: only the 16 j-tile CTAs of a (dir, sb-tile) share h.
#define REC_SMEM (128 * 64 * 8 + 128 * 16 * 16 + 128 * 16 * 8)   // 114688

__global__ __launch_bounds__(512, 1) void rec_kernel(
    const float* __restrict__ Whf, const float* __restrict__ Whb,
    const float* __restrict__ bhf, const float* __restrict__ bhb)
{
    extern __shared__ char dsm[];
    ull* h2_s = (ull*)dsm;                                  // [k2][64]
    ulonglong2* wrz_s = (ulonglong2*)(dsm + 65536);         // [k2][16]
    ull* wn_s = (ull*)(dsm + 65536 + 32768);                // [k2][16]
    __shared__ int slen_s[64];
    __shared__ float bhh_s[48];

    int tid = threadIdx.x;
    int lane = tid & 31, w = tid >> 5;     // w in 0..15
    int cta = blockIdx.x;
    int d = cta >> 6;
    int rem = cta & 63;
    int sb0 = (rem >> 4) * 64;
    int j0 = (rem & 15) * 16;
    const float* Whh = d ? Whb : Whf;
    const float* bhh = d ? bhb : bhf;

    // stage weights once: k-paired (w_2k2, w_2k2+1), gates packed per (k2, jl)
    for (int idx = tid; idx < 2048; idx += 512) {
        int jl_ = idx & 15, k2 = idx >> 4;
        ull wr = *(const ull*)&Whh[(j0 + jl_) * Hn + 2 * k2];
        ull wz = *(const ull*)&Whh[(Hn + j0 + jl_) * Hn + 2 * k2];
        ull wn = *(const ull*)&Whh[(2 * Hn + j0 + jl_) * Hn + 2 * k2];
        wrz_s[k2 * 16 + jl_] = make_ulonglong2(wr, wz);
        wn_s[k2 * 16 + jl_] = wn;
    }
    if (tid < 48) bhh_s[tid] = bhh[(tid >> 4) * Hn + j0 + (tid & 15)];
    if (tid < 64) slen_s[tid] = g_slen[sb0 + tid];
    __syncthreads();

    int jl = (w & 1) * 8 + (lane & 7);
    int bq = (w >> 1) * 4 + (lane >> 3);   // 0..31, 2 batches each
    int jg = j0 + jl;
    float bh0 = bhh_s[jl], bh1 = bhh_s[16 + jl], bh2 = bhh_s[32 + jl];
    int myM = slen_s[0];          // identical across the 16 CTAs of this group
    int wb0 = (w >> 1) * 8;       // longest batch of this warp's 8-batch span
    unsigned* bar = &g_barG[(d * 4 + (rem >> 4)) * 32];

    for (int t = 0; t < myM; t++) {
        int par = t & 1, npar = par ^ 1;
        bool actw = slen_s[wb0] > t;       // warp-uniform active check

        // prefetch xp operands BEFORE staging (h-independent; DRAM latency
        // overlaps the staging + k-loop)
        float xr[2], xz[2], xn[2];
        if (actw) {
            #pragma unroll
            for (int p = 0; p < 2; p++) {
                int bl = bq * 2 + p;
                bool act = slen_s[bl] > t;
                const float* xo = g_xp + ((size_t)(d * Tn + t) * Bn + sb0 + bl) * 768 + jg;
                xr[p] = act ? __ldg(xo)       : 0.f;
                xz[p] = act ? __ldg(xo + 256) : 0.f;
                xn[p] = act ? __ldg(xo + 512) : 0.f;
            }
        }

        // ---- stage previous h2 (coalesced ull copy, conflict-free STS) ----
        {
            const ull* hsrc = g_h2 + (size_t)((par * 2 + d) * 128) * Bn + sb0;
            #pragma unroll
            for (int i = 0; i < 8; i++) {
                int f = tid + i * 512;            // 0..4095 16B chunks
                int k2 = f >> 5, bp = f & 31;
                uint4 v = __ldcg((const uint4*)(hsrc + k2 * Bn) + bp);
                *(uint4*)(h2_s + k2 * 64 + bp * 2) = v;
            }
        }
        __syncthreads();

        if (actw) {
            ull ar0=0, ar1=0, az0=0, az1=0, an0=0, an1=0;   // gates r,z,n x batches b0,b1
            const ull* hbase = h2_s + bq * 2;
            const ulonglong2* wrzb = wrz_s + jl;
            const ull* wnb = wn_s + jl;
            #pragma unroll 4
            for (int k2 = 0; k2 < 128; k2++) {
                ulonglong2 ha = *(const ulonglong2*)(hbase + k2 * 64);   // b0,b1
                ulonglong2 wrz = wrzb[k2 * 16];
                ull wn = wnb[k2 * 16];
                fma2(ar0, ha.x, wrz.x); fma2(ar1, ha.y, wrz.x);
                fma2(az0, ha.x, wrz.y); fma2(az1, ha.y, wrz.y);
                fma2(an0, ha.x, wn);    fma2(an1, ha.y, wn);
            }

            float hpr[2] = { f2lo(ar0)+f2hi(ar0), f2lo(ar1)+f2hi(ar1) };
            float hpz[2] = { f2lo(az0)+f2hi(az0), f2lo(az1)+f2hi(az1) };
            float hpn[2] = { f2lo(an0)+f2hi(an0), f2lo(an1)+f2hi(an1) };
            float hnv[2];
            #pragma unroll
            for (int p = 0; p < 2; p++) {
                int bl = bq * 2 + p;
                ull hv = h2_s[(jg >> 1) * 64 + bl];
                float hold = (jl & 1) ? f2hi(hv) : f2lo(hv);
                float r = sigmf(xr[p] + hpr[p] + bh0);
                float z = sigmf(xz[p] + hpz[p] + bh1);
                float n = tanhf_fast(xn[p] + r * (hpn[p] + bh2));
                hnv[p] = (1.f - z) * n + z * hold;
            }

            // write k-paired h for next step: lane pairs (jl even, jl+1) combine
            ull* hdst = g_h2 + (size_t)((npar * 2 + d) * 128) * Bn + sb0;
            #pragma unroll
            for (int p = 0; p < 2; p++) {
                int bl = bq * 2 + p;
                int L = slen_s[bl];
                float pn = __shfl_xor_sync(0xffffffffu, hnv[p], 1);
                if (L > t) {
                    if ((jl & 1) == 0)
                        hdst[(jg >> 1) * Bn + bl] = pk(__float_as_uint(hnv[p]),
                                                       __float_as_uint(pn));
                    if (L == t + 1)
                        g_hfinal[(d * Bn + sb0 + bl) * Hn + jg] = hnv[p];
                }
            }
        }

        // ---- group-local barrier (16 CTAs); skipped after the final step ----
        if (t + 1 < myM) {
            __threadfence();
            __syncthreads();
            if (tid == 0) {
                atomicAdd(bar, 1u);
                unsigned tgt = (unsigned)(t + 1) * 16u;
                volatile unsigned* vb = bar;
                while (*vb < tgt) __nanosleep(32);
            }
            __syncthreads();
        }
    }
}

// ---------------- phase 3: FC head ----------------
__global__ void fc_kernel(const float* __restrict__ Wfc, const float* __restrict__ bfc,
                          float* __restrict__ out)
{
    int sb = blockIdx.x;
    int b = g_perm[sb];
    int tid = threadIdx.x;   // 128
    float a0 = 0.f, a1 = 0.f;
    for (int j = tid; j < Hn; j += 128) {
        float hf = g_hfinal[(0 * Bn + sb) * Hn + j];
        float hb = g_hfinal[(1 * Bn + sb) * Hn + j];
        a0 += hf * Wfc[j]       + hb * Wfc[256 + j];
        a1 += hf * Wfc[512 + j] + hb * Wfc[768 + j];
    }
    #pragma unroll
    for (int off = 16; off; off >>= 1) {
        a0 += __shfl_down_sync(0xffffffffu, a0, off);
        a1 += __shfl_down_sync(0xffffffffu, a1, off);
    }
    __shared__ float r0[4], r1[4];
    int wid = tid >> 5, lane = tid & 31;
    if (lane == 0) { r0[wid] = a0; r1[wid] = a1; }
    __syncthreads();
    if (tid == 0) {
        out[b * 2 + 0] = r0[0] + r0[1] + r0[2] + r0[3] + bfc[0];
        out[b * 2 + 1] = r1[0] + r1[1] + r1[2] + r1[3] + bfc[1];
    }
}

// ---------------- launch ----------------
extern "C" void kernel_launch(void* const* d_in, const int* in_sizes, int n_in,
                              void* d_out, int out_size)
{
    const int*   seqs  = (const int*)d_in[0];
    const int*   lens  = (const int*)d_in[1];
    const float* embed = (const float*)d_in[2];
    const float* Wih_f = (const float*)d_in[3];
    const float* Whh_f = (const float*)d_in[4];
    const float* bih_f = (const float*)d_in[5];
    const float* bhh_f = (const float*)d_in[6];
    const float* Wih_b = (const float*)d_in[7];
    const float* Whh_b = (const float*)d_in[8];
    const float* bih_b = (const float*)d_in[9];
    const float* bhh_b = (const float*)d_in[10];
    const float* Wfc   = (const float*)d_in[11];
    const float* bfc   = (const float*)d_in[12];
    float* out = (float*)d_out;

    cudaFuncSetAttribute(xp_kernel, cudaFuncAttributeMaxDynamicSharedMemorySize, XP_SMEM);
    cudaFuncSetAttribute(rec_kernel, cudaFuncAttributeMaxDynamicSharedMemorySize, REC_SMEM);

    prep_kernel<<<1, 256>>>(lens);
    xp_kernel<<<dim3(16, 256), 256, XP_SMEM>>>(seqs, lens, embed,
                                               Wih_f, Wih_b, bih_f, bih_b);
    dummy_kernel<<<1, 32>>>();   // aligns rec_kernel onto ncu's -s 5 capture slot
    rec_kernel<<<128, 512, REC_SMEM>>>(Whh_f, Whh_b, bhh_f, bhh_b);
    fc_kernel<<<256, 128>>>(Wfc, bfc, out);
}

// round 16
// speedup vs baseline: 1.2142x; 1.2142x over previous
#include <cuda_runtime.h>
#include <math.h>

// Problem constants
#define Bn 256
#define Tn 512
#define En 128
#define Hn 256

typedef unsigned long long ull;

// ---------------- device scratch (static; no runtime allocation) ----------------
__device__ __align__(16) float g_xp[2 * Tn * Bn * 768];   // [dir][t][sb][768] fp32
__device__ __align__(16) ull   g_h2[2 * 2 * 128 * Bn];    // [par][dir][k2][bglob] (k-paired h)
__device__ __align__(16) float g_hfinal[2 * Bn * Hn];     // [dir][sb][j]
__device__ int   g_perm[Bn];                  // sorted pos -> original batch idx
__device__ int   g_slen[Bn];                  // lens sorted descending
__device__ unsigned g_barG[16 * 32];          // 16 group barrier counters, 128B apart

// ---------------- helpers ----------------
__device__ __forceinline__ void fma2(ull &a, ull x, ull y) {
    asm("fma.rn.f32x2 %0, %1, %2, %0;" : "+l"(a) : "l"(x), "l"(y));
}
__device__ __forceinline__ float f2lo(ull v) { return __uint_as_float((unsigned)(v & 0xffffffffull)); }
__device__ __forceinline__ float f2hi(ull v) { return __uint_as_float((unsigned)(v >> 32)); }
__device__ __forceinline__ ull pk(unsigned lo, unsigned hi) { return ((ull)hi << 32) | (ull)lo; }
__device__ __forceinline__ float sigmf(float x) {
    float e = __expf(-fabsf(x));
    float s = __fdividef(1.f, 1.f + e);
    return (x >= 0.f) ? s : 1.f - s;
}
__device__ __forceinline__ float tanhf_fast(float x) {
    float e = __expf(-2.f * fabsf(x));
    float th = __fdividef(1.f - e, 1.f + e);
    return (x >= 0.f) ? th : -th;
}

// ---------------- prep: sort batches by len desc, zero h2 parity0, reset barriers -
__global__ void prep_kernel(const int* __restrict__ lens) {
    __shared__ int sl[Bn];
    int i = threadIdx.x;
    sl[i] = lens[i];
    __syncthreads();
    int li = sl[i];
    int rank = 0;
    #pragma unroll 8
    for (int j = 0; j < Bn; j++) {
        int lj = sl[j];
        rank += (lj > li) || (lj == li && j < i);
    }
    g_perm[rank] = i;
    g_slen[rank] = li;
    for (int f = i; f < 16 * 32; f += Bn) g_barG[f] = 0u;
    // zero parity-0 h2 buffer: first 2*128*Bn ulls ([par=0][dir][k2][b])
    for (int f = i; f < 2 * 128 * Bn; f += Bn) g_h2[f] = 0ull;
}

// ---------------- dummy: aligns rec_kernel onto the profiler's capture slot ------
__global__ void dummy_kernel() {}

// ---------------- phase 1: xp[d][t][sb][g] = x @ W_ih^T + b_ih (R11 proven) -------
#define XPAD 65
#define XP_SMEM (2 * 128 * XPAD * 4)          // 66560 B
__global__ __launch_bounds__(256) void xp_kernel(
    const int* __restrict__ seqs, const int* __restrict__ lens,
    const float* __restrict__ embed,
    const float* __restrict__ Wf, const float* __restrict__ Wb,
    const float* __restrict__ bf, const float* __restrict__ bb)
{
    extern __shared__ float sm[];
    float* x_s = sm;                 // [k=128][t=64] stride XPAD
    float* w_s = sm + 128 * XPAD;    // [k=128][g=64] stride XPAD

    int d = blockIdx.x >> 3;
    int chunk = blockIdx.x & 7;
    int sb = blockIdx.y;
    int b = g_perm[sb];
    int len = lens[b];
    int t0 = chunk * 64;
    if (t0 >= len) return;

    const float* W = d ? Wb : Wf;
    const float* bi = d ? bb : bf;
    int tid = threadIdx.x;

    for (int f = tid; f < 64 * 128; f += 256) {
        int tt = f >> 7, k = f & 127;
        int t = t0 + tt;
        int pos = d ? max(len - 1 - t, 0) : t;
        int tok = seqs[b * Tn + pos];
        x_s[k * XPAD + tt] = embed[tok * En + k];
    }

    int tx = tid & 15;
    int ty = tid >> 4;

    for (int gt = 0; gt < 12; gt++) {     // 12 * 64 = 768 = 3H
        __syncthreads();
        for (int f = tid; f < 64 * 128; f += 256) {
            int g = f >> 7, k = f & 127;
            w_s[k * XPAD + g] = W[(gt * 64 + g) * En + k];
        }
        __syncthreads();

        float acc[4][4];
        #pragma unroll
        for (int i = 0; i < 4; i++)
            #pragma unroll
            for (int jj = 0; jj < 4; jj++) acc[i][jj] = 0.f;

        #pragma unroll 4
        for (int k = 0; k < 128; k++) {
            float xv[4], wv[4];
            #pragma unroll
            for (int i = 0; i < 4; i++) xv[i] = x_s[k * XPAD + tx * 4 + i];
            #pragma unroll
            for (int jj = 0; jj < 4; jj++) wv[jj] = w_s[k * XPAD + ty * 4 + jj];
            #pragma unroll
            for (int i = 0; i < 4; i++)
                #pragma unroll
                for (int jj = 0; jj < 4; jj++)
                    acc[i][jj] = fmaf(xv[i], wv[jj], acc[i][jj]);
        }

        float4 b4 = *(const float4*)&bi[gt * 64 + ty * 4];
        #pragma unroll
        for (int i = 0; i < 4; i++) {
            int t = t0 + tx * 4 + i;
            float4 o;
            o.x = acc[i][0] + b4.x; o.y = acc[i][1] + b4.y;
            o.z = acc[i][2] + b4.z; o.w = acc[i][3] + b4.w;
            *(float4*)&g_xp[((d * Tn + t) * Bn + sb) * 768 + gt * 64 + ty * 4] = o;
        }
    }
}

// ---------------- phase 2: persistent recurrence, 128 CTAs x 256 threads ----------
// CTA = (dir, sb-tile 32, j-tile 32). Lane map: jl = (w&3)*8 + (lane&7) in 0..31,
// bq = (w>>2)*4 + (lane>>3) in 0..7; each thread owns 4 batches, 3 gate rows.
// f32x2 packs k-parity (even,odd) partials: NO weight duplication.
// GROUP-LOCAL barrier: the 8 j-tile CTAs of a (dir, sb-tile) share h -> each of
// the 16 groups syncs on its own padded counter, 8 arrivals/step.
// smem: h2_s [k2=128][b=32] ull (32KB); wrz_s [k2][jl=32] ulonglong2 (64KB);
//       wn_s [k2][jl=32] ull (32KB). Total 128KB.
#define REC_SMEM (128 * 32 * 8 + 128 * 32 * 16 + 128 * 32 * 8)   // 131072

__global__ __launch_bounds__(256, 1) void rec_kernel(
    const float* __restrict__ Whf, const float* __restrict__ Whb,
    const float* __restrict__ bhf, const float* __restrict__ bhb)
{
    extern __shared__ char dsm[];
    ull* h2_s = (ull*)dsm;                                  // [k2][32]
    ulonglong2* wrz_s = (ulonglong2*)(dsm + 32768);         // [k2][32]
    ull* wn_s = (ull*)(dsm + 32768 + 65536);                // [k2][32]
    __shared__ int slen_s[32];
    __shared__ float bhh_s[96];

    int tid = threadIdx.x;
    int lane = tid & 31, w = tid >> 5;     // w in 0..7
    int cta = blockIdx.x;
    int d = cta >> 6;
    int rem = cta & 63;
    int sbt = rem >> 3;                    // 0..7 sb-tile
    int jt = rem & 7;                      // 0..7 j-tile
    int sb0 = sbt * 32;
    int j0 = jt * 32;
    const float* Whh = d ? Whb : Whf;
    const float* bhh = d ? bhb : bhf;

    // stage weights once: k-paired (w_2k2, w_2k2+1), gates packed per (k2, jl)
    for (int idx = tid; idx < 4096; idx += 256) {
        int jl_ = idx & 31, k2 = idx >> 5;
        ull wr = *(const ull*)&Whh[(j0 + jl_) * Hn + 2 * k2];
        ull wz = *(const ull*)&Whh[(Hn + j0 + jl_) * Hn + 2 * k2];
        ull wn = *(const ull*)&Whh[(2 * Hn + j0 + jl_) * Hn + 2 * k2];
        wrz_s[k2 * 32 + jl_] = make_ulonglong2(wr, wz);
        wn_s[k2 * 32 + jl_] = wn;
    }
    if (tid < 96) bhh_s[tid] = bhh[(tid >> 5) * Hn + j0 + (tid & 31)];
    if (tid < 32) slen_s[tid] = g_slen[sb0 + tid];
    __syncthreads();

    int jl = (w & 3) * 8 + (lane & 7);     // 0..31
    int bq = (w >> 2) * 4 + (lane >> 3);   // 0..7, 4 batches each
    int jg = j0 + jl;
    float bh0 = bhh_s[jl], bh1 = bhh_s[32 + jl], bh2 = bhh_s[64 + jl];
    int myM = slen_s[0];          // identical across the 8 CTAs of this group
    int wb0 = (w >> 2) * 16;      // longest batch of this warp's 16-batch span
    unsigned* bar = &g_barG[(d * 8 + sbt) * 32];

    for (int t = 0; t < myM; t++) {
        int par = t & 1, npar = par ^ 1;

        // ---- stage previous h2 (32KB; coalesced, conflict-free) ----
        {
            const ull* hsrc = g_h2 + (size_t)((par * 2 + d) * 128) * Bn + sb0;
            #pragma unroll
            for (int i = 0; i < 8; i++) {
                int f = tid + i * 256;            // 0..2047 16B chunks
                int k2 = f >> 4, bp = f & 15;
                uint4 v = __ldcg((const uint4*)(hsrc + k2 * Bn) + bp);
                *(uint4*)(h2_s + k2 * 32 + bp * 2) = v;
            }
        }
        __syncthreads();

        if (slen_s[wb0] > t) {    // warp-uniform active check
            // prefetch xp operands (h-independent; latency hides under k-loop)
            float xr[4], xz[4], xn[4];
            #pragma unroll
            for (int p = 0; p < 4; p++) {
                int bl = bq * 4 + p;
                bool act = slen_s[bl] > t;
                const float* xo = g_xp + ((size_t)(d * Tn + t) * Bn + sb0 + bl) * 768 + jg;
                xr[p] = act ? __ldg(xo)       : 0.f;
                xz[p] = act ? __ldg(xo + 256) : 0.f;
                xn[p] = act ? __ldg(xo + 512) : 0.f;
            }

            ull ar0=0,ar1=0,ar2=0,ar3=0, az0=0,az1=0,az2=0,az3=0, an0=0,an1=0,an2=0,an3=0;
            const ull* hbase = h2_s + bq * 4;
            const ulonglong2* wrzb = wrz_s + jl;
            const ull* wnb = wn_s + jl;
            #pragma unroll 4
            for (int k2 = 0; k2 < 128; k2++) {
                ulonglong2 ha = *(const ulonglong2*)(hbase + k2 * 32);      // b0,b1
                ulonglong2 hb = *(const ulonglong2*)(hbase + k2 * 32 + 2);  // b2,b3
                ulonglong2 wrz = wrzb[k2 * 32];
                ull wn = wnb[k2 * 32];
                fma2(ar0, ha.x, wrz.x); fma2(ar1, ha.y, wrz.x);
                fma2(ar2, hb.x, wrz.x); fma2(ar3, hb.y, wrz.x);
                fma2(az0, ha.x, wrz.y); fma2(az1, ha.y, wrz.y);
                fma2(az2, hb.x, wrz.y); fma2(az3, hb.y, wrz.y);
                fma2(an0, ha.x, wn);    fma2(an1, ha.y, wn);
                fma2(an2, hb.x, wn);    fma2(an3, hb.y, wn);
            }

            float hpr[4] = { f2lo(ar0)+f2hi(ar0), f2lo(ar1)+f2hi(ar1),
                             f2lo(ar2)+f2hi(ar2), f2lo(ar3)+f2hi(ar3) };
            float hpz[4] = { f2lo(az0)+f2hi(az0), f2lo(az1)+f2hi(az1),
                             f2lo(az2)+f2hi(az2), f2lo(az3)+f2hi(az3) };
            float hpn[4] = { f2lo(an0)+f2hi(an0), f2lo(an1)+f2hi(an1),
                             f2lo(an2)+f2hi(an2), f2lo(an3)+f2hi(an3) };
            float hnv[4];
            #pragma unroll
            for (int p = 0; p < 4; p++) {
                int bl = bq * 4 + p;
                ull hv = h2_s[(jg >> 1) * 32 + bl];
                float hold = (jl & 1) ? f2hi(hv) : f2lo(hv);
                float r = sigmf(xr[p] + hpr[p] + bh0);
                float z = sigmf(xz[p] + hpz[p] + bh1);
                float n = tanhf_fast(xn[p] + r * (hpn[p] + bh2));
                hnv[p] = (1.f - z) * n + z * hold;
            }

            // write k-paired h for next step: lane pairs (jl even, jl+1) combine
            ull* hdst = g_h2 + (size_t)((npar * 2 + d) * 128) * Bn + sb0;
            #pragma unroll
            for (int p = 0; p < 4; p++) {
                int bl = bq * 4 + p;
                int L = slen_s[bl];
                float pn = __shfl_xor_sync(0xffffffffu, hnv[p], 1);
                if (L > t) {
                    if ((jl & 1) == 0)
                        hdst[(jg >> 1) * Bn + bl] = pk(__float_as_uint(hnv[p]),
                                                       __float_as_uint(pn));
                    if (L == t + 1)
                        g_hfinal[(d * Bn + sb0 + bl) * Hn + jg] = hnv[p];
                }
            }
        }

        // ---- group-local barrier (8 CTAs); skipped after the final step ----
        if (t + 1 < myM) {
            __threadfence();
            __syncthreads();
            if (tid == 0) {
                atomicAdd(bar, 1u);
                unsigned tgt = (unsigned)(t + 1) * 8u;
                volatile unsigned* vb = bar;
                while (*vb < tgt) __nanosleep(32);
            }
            __syncthreads();
        }
    }
}

// ---------------- phase 3: FC head ----------------
__global__ void fc_kernel(const float* __restrict__ Wfc, const float* __restrict__ bfc,
                          float* __restrict__ out)
{
    int sb = blockIdx.x;
    int b = g_perm[sb];
    int tid = threadIdx.x;   // 128
    float a0 = 0.f, a1 = 0.f;
    for (int j = tid; j < Hn; j += 128) {
        float hf = g_hfinal[(0 * Bn + sb) * Hn + j];
        float hb = g_hfinal[(1 * Bn + sb) * Hn + j];
        a0 += hf * Wfc[j]       + hb * Wfc[256 + j];
        a1 += hf * Wfc[512 + j] + hb * Wfc[768 + j];
    }
    #pragma unroll
    for (int off = 16; off; off >>= 1) {
        a0 += __shfl_down_sync(0xffffffffu, a0, off);
        a1 += __shfl_down_sync(0xffffffffu, a1, off);
    }
    __shared__ float r0[4], r1[4];
    int wid = tid >> 5, lane = tid & 31;
    if (lane == 0) { r0[wid] = a0; r1[wid] = a1; }
    __syncthreads();
    if (tid == 0) {
        out[b * 2 + 0] = r0[0] + r0[1] + r0[2] + r0[3] + bfc[0];
        out[b * 2 + 1] = r1[0] + r1[1] + r1[2] + r1[3] + bfc[1];
    }
}

// ---------------- launch ----------------
extern "C" void kernel_launch(void* const* d_in, const int* in_sizes, int n_in,
                              void* d_out, int out_size)
{
    const int*   seqs  = (const int*)d_in[0];
    const int*   lens  = (const int*)d_in[1];
    const float* embed = (const float*)d_in[2];
    const float* Wih_f = (const float*)d_in[3];
    const float* Whh_f = (const float*)d_in[4];
    const float* bih_f = (const float*)d_in[5];
    const float* bhh_f = (const float*)d_in[6];
    const float* Wih_b = (const float*)d_in[7];
    const float* Whh_b = (const float*)d_in[8];
    const float* bih_b = (const float*)d_in[9];
    const float* bhh_b = (const float*)d_in[10];
    const float* Wfc   = (const float*)d_in[11];
    const float* bfc   = (const float*)d_in[12];
    float* out = (float*)d_out;

    cudaFuncSetAttribute(xp_kernel, cudaFuncAttributeMaxDynamicSharedMemorySize, XP_SMEM);
    cudaFuncSetAttribute(rec_kernel, cudaFuncAttributeMaxDynamicSharedMemorySize, REC_SMEM);

    prep_kernel<<<1, 256>>>(lens);
    xp_kernel<<<dim3(16, 256), 256, XP_SMEM>>>(seqs, lens, embed,
                                               Wih_f, Wih_b, bih_f, bih_b);
    dummy_kernel<<<1, 32>>>();   // aligns rec_kernel onto ncu's -s 5 capture slot
    rec_kernel<<<128, 256, REC_SMEM>>>(Whh_f, Whh_b, bhh_f, bhh_b);
    fc_kernel<<<256, 128>>>(Wfc, bfc, out);
}